// round 3
// baseline (speedup 1.0000x reference)
#include <cuda_runtime.h>
#include <cuda_bf16.h>
#include <math.h>

#define BATCH 16
#define CIN   512
#define FH    50
#define FW    50
#define HW    2500
#define NANCH 9
#define NTOT  (HW*NANCH)      // 22500
#define PRE   512
#define POST  128
#define IMGW  800.0f
#define IMGH  800.0f

// Kahan compensated accumulation, contraction-proof via intrinsics.
// Final high-accuracy result = s - c.
#define KAHAN_ADD(s, c, p) do {                        \
    float _y = __fsub_rn((p), (c));                    \
    float _t = __fadd_rn((s), _y);                     \
    (c) = __fsub_rn(__fsub_rn(_t, (s)), _y);           \
    (s) = _t;                                          \
} while (0)

// ---------------- device scratch (static, no allocation) ----------------
__device__ float g_shared[(size_t)BATCH*CIN*HW];   // post-ReLU conv1 activations
__device__ float g_scores[(size_t)BATCH*NTOT];     // sigmoid cls scores, [b][p*9+a]
__device__ int   g_topidx[BATCH*PRE];
__device__ float g_topscore[BATCH*PRE];

// ================= K1: 3x3 conv (512->512) + bias + ReLU =================
// Kahan-compensated accumulation -> near-exact f32 conv result.
__global__ __launch_bounds__(256) void conv3x3_kernel(
    const float* __restrict__ x, const float* __restrict__ w1,
    const float* __restrict__ b1)
{
    __shared__ float Ws[9][64];
    __shared__ float Xs[5][52];

    const int bidx = blockIdx.z;
    const int oc0  = blockIdx.y * 64;
    const int p0   = blockIdx.x * 64;
    const int tid  = threadIdx.x;
    const int tx   = tid & 15;     // pixel group
    const int ty   = tid >> 4;     // oc group

    const int yA = p0 / FW;

    int  pj[4], rj[4], cj[4];
    bool inb[4];
#pragma unroll
    for (int jj = 0; jj < 4; jj++) {
        int p = p0 + tx*4 + jj;
        pj[jj] = p;
        int py = p / FW, pxx = p % FW;
        rj[jj] = py - yA + 1;
        cj[jj] = pxx + 1;
        inb[jj] = (p < HW);
    }

    float acc[4][4], cmp[4][4];
#pragma unroll
    for (int i = 0; i < 4; i++)
#pragma unroll
        for (int j = 0; j < 4; j++) { acc[i][j] = 0.f; cmp[i][j] = 0.f; }

    const float* xb = x + (size_t)bidx * CIN * HW;

    for (int ic = 0; ic < CIN; ic++) {
        for (int i = tid; i < 576; i += 256) {
            int t = i / 64, o = i % 64;
            Ws[t][o] = w1[((size_t)(oc0 + o)) * (CIN*9) + ic*9 + t];
        }
        const float* xc = xb + (size_t)ic * HW;
        for (int i = tid; i < 5*52; i += 256) {
            int rr = i / 52, cc = i % 52;
            int yy = yA - 1 + rr, xx = cc - 1;
            Xs[rr][cc] = (yy >= 0 && yy < FH && xx >= 0 && xx < FW)
                             ? xc[yy*FW + xx] : 0.f;
        }
        __syncthreads();

#pragma unroll
        for (int t = 0; t < 9; t++) {
            const int dy = t/3 - 1, dx = t%3 - 1;
            float a0 = Ws[t][ty*4+0];
            float a1 = Ws[t][ty*4+1];
            float a2 = Ws[t][ty*4+2];
            float a3 = Ws[t][ty*4+3];
#pragma unroll
            for (int jj = 0; jj < 4; jj++) {
                float bv = Xs[rj[jj]+dy][cj[jj]+dx];
                KAHAN_ADD(acc[0][jj], cmp[0][jj], __fmul_rn(a0, bv));
                KAHAN_ADD(acc[1][jj], cmp[1][jj], __fmul_rn(a1, bv));
                KAHAN_ADD(acc[2][jj], cmp[2][jj], __fmul_rn(a2, bv));
                KAHAN_ADD(acc[3][jj], cmp[3][jj], __fmul_rn(a3, bv));
            }
        }
        __syncthreads();
    }

#pragma unroll
    for (int ii = 0; ii < 4; ii++) {
        int oc = oc0 + ty*4 + ii;
        float bias = b1[oc];
#pragma unroll
        for (int jj = 0; jj < 4; jj++) {
            if (inb[jj]) {
                float r = __fsub_rn(acc[ii][jj], cmp[ii][jj]);   // conv result
                float v = __fadd_rn(r, bias);                    // + bias (f32)
                g_shared[((size_t)bidx*CIN + oc)*HW + pj[jj]] = fmaxf(v, 0.f);
            }
        }
    }
}

// ================= K2: 1x1 cls conv (512->9) + sigmoid ==================
__global__ __launch_bounds__(256) void cls_kernel(
    const float* __restrict__ w2, const float* __restrict__ b2)
{
    __shared__ float w2s[9][512];
    const int b = blockIdx.y;
    const int p = blockIdx.x * 256 + threadIdx.x;
    for (int i = threadIdx.x; i < 9*512; i += 256)
        w2s[i/512][i%512] = w2[i];
    __syncthreads();
    if (p >= HW) return;

    float acc[9], cmp[9];
#pragma unroll
    for (int a = 0; a < 9; a++) { acc[a] = 0.f; cmp[a] = 0.f; }

    const float* sp = g_shared + (size_t)b * CIN * HW + p;
    for (int c = 0; c < CIN; c++) {
        float v = sp[(size_t)c * HW];
#pragma unroll
        for (int a = 0; a < 9; a++)
            KAHAN_ADD(acc[a], cmp[a], __fmul_rn(v, w2s[a][c]));
    }
    float* outp = g_scores + (size_t)b * NTOT + (size_t)p * 9;
#pragma unroll
    for (int a = 0; a < 9; a++) {
        float logit = __fadd_rn(__fsub_rn(acc[a], cmp[a]), b2[a]);
        double sg = 1.0 / (1.0 + exp(-(double)logit));   // correctly-rounded sigmoid
        outp[a] = (float)sg;
    }
}

// ================= K3: exact per-image top-512 (sorted) ==================
__global__ __launch_bounds__(1024) void topk_kernel()
{
    extern __shared__ unsigned char smraw[];
    unsigned int* hist = (unsigned int*)smraw;                 // 32768
    unsigned int* csum = hist + 32768;                         // 1024
    unsigned long long* cand = (unsigned long long*)(csum + 1024); // 1024
    __shared__ int s_tb, s_cntgt, s_thr, s_cnt;

    const int b = blockIdx.x, tid = threadIdx.x;
    const float* sc = g_scores + (size_t)b * NTOT;

    for (int i = tid; i < 32768; i += 1024) hist[i] = 0;
    __syncthreads();
    for (int i = tid; i < NTOT; i += 1024) {
        unsigned int bits = __float_as_uint(sc[i]);
        atomicAdd(&hist[bits >> 15], 1u);
    }
    __syncthreads();
    { unsigned int cs = 0;
#pragma unroll 4
      for (int k = 0; k < 32; k++) cs += hist[tid*32 + k];
      csum[tid] = cs; }
    __syncthreads();
    if (tid == 0) {
        unsigned int accum = 0;
        int ch = 1023;
        for (; ch > 0; ch--) { if (accum + csum[ch] >= PRE) break; accum += csum[ch]; }
        int bk = ch*32 + 31;
        for (; bk > ch*32; bk--) { if (accum + hist[bk] >= PRE) break; accum += hist[bk]; }
        s_tb = bk; s_cntgt = (int)accum;
    }
    __syncthreads();
    const int tb = s_tb, cntgt = s_cntgt;

    for (int i = tid; i < 32768; i += 1024) hist[i] = 0;
    __syncthreads();
    for (int i = tid; i < NTOT; i += 1024) {
        unsigned int bits = __float_as_uint(sc[i]);
        if ((int)(bits >> 15) == tb) atomicAdd(&hist[bits & 0x7FFF], 1u);
    }
    __syncthreads();
    { unsigned int cs = 0;
#pragma unroll 4
      for (int k = 0; k < 32; k++) cs += hist[tid*32 + k];
      csum[tid] = cs; }
    __syncthreads();
    if (tid == 0) {
        unsigned int accum = (unsigned int)cntgt;
        int ch = 1023;
        for (; ch > 0; ch--) { if (accum + csum[ch] >= PRE) break; accum += csum[ch]; }
        int bk = ch*32 + 31;
        for (; bk > ch*32; bk--) { if (accum + hist[bk] >= PRE) break; accum += hist[bk]; }
        s_thr = (tb << 15) | bk;
        s_cnt = 0;
    }
    __syncthreads();
    const unsigned int thrbits = (unsigned int)s_thr;

    for (int i = tid; i < NTOT; i += 1024) {
        unsigned int bits = __float_as_uint(sc[i]);
        if (bits >= thrbits) {
            int pos = atomicAdd(&s_cnt, 1);
            if (pos < 1024)
                cand[pos] = ((unsigned long long)bits << 32) |
                            (unsigned long long)(0xFFFFFFFFu - (unsigned int)i);
        }
    }
    __syncthreads();
    int cnt = s_cnt; if (cnt > 1024) cnt = 1024;
    if (tid >= cnt) cand[tid] = 0ULL;
    __syncthreads();

    for (int k = 2; k <= 1024; k <<= 1) {
        for (int j = k >> 1; j > 0; j >>= 1) {
            int ixj = tid ^ j;
            if (ixj > tid) {
                unsigned long long a = cand[tid], c = cand[ixj];
                bool up = ((tid & k) == 0);
                bool sw = up ? (a < c) : (a > c);
                if (sw) { cand[tid] = c; cand[ixj] = a; }
            }
            __syncthreads();
        }
    }

    if (tid < PRE) {
        unsigned long long key = cand[tid];
        unsigned int idx = 0xFFFFFFFFu - (unsigned int)(key & 0xFFFFFFFFull);
        g_topidx[b*PRE + tid]   = (int)idx;
        g_topscore[b*PRE + tid] = __uint_as_float((unsigned int)(key >> 32));
    }
}

// ====== K4: offsets@selected + anchors + decode + clip + NMS + output ====
#define W3S_FLOATS (36*513)    // 18468 floats, multiple of 4 -> 16B aligned end
__global__ __launch_bounds__(512) void proposal_kernel(
    const float* __restrict__ w3, const float* __restrict__ b3,
    float* __restrict__ out)
{
    extern __shared__ float sm[];
    float*  w3s   = sm;
    float4* boxes = (float4*)(sm + W3S_FLOATS);
    float*  ss    = (float*)(boxes + PRE);
    int*    keep  = (int*)(ss + PRE);
    __shared__ int warpcnt[16];

    const int b = blockIdx.x;
    const int j = threadIdx.x;

    for (int i = j; i < 36*512; i += 512) {
        int row = i >> 9, c = i & 511;
        w3s[row*513 + c] = w3[i];
    }
    __syncthreads();

    const int   idx = g_topidx[b*PRE + j];
    const float s   = g_topscore[b*PRE + j];
    const int p = idx / 9, a = idx % 9;

    // regression offsets (Kahan, bias at end)
    float so[4] = {0.f,0.f,0.f,0.f}, co[4] = {0.f,0.f,0.f,0.f};
    {
        const float* col = g_shared + (size_t)b * CIN * HW + p;
        const float* w0 = w3s + (a*4+0)*513;
        const float* w1r= w3s + (a*4+1)*513;
        const float* w2r= w3s + (a*4+2)*513;
        const float* w3r= w3s + (a*4+3)*513;
        for (int c = 0; c < CIN; c++) {
            float v = col[(size_t)c * HW];
            KAHAN_ADD(so[0], co[0], __fmul_rn(v, w0[c]));
            KAHAN_ADD(so[1], co[1], __fmul_rn(v, w1r[c]));
            KAHAN_ADD(so[2], co[2], __fmul_rn(v, w2r[c]));
            KAHAN_ADD(so[3], co[3], __fmul_rn(v, w3r[c]));
        }
    }
    const float o0 = __fadd_rn(__fsub_rn(so[0], co[0]), b3[a*4+0]);
    const float o1 = __fadd_rn(__fsub_rn(so[1], co[1]), b3[a*4+1]);
    const float o2 = __fadd_rn(__fsub_rn(so[2], co[2]), b3[a*4+2]);
    const float o3 = __fadd_rn(__fsub_rn(so[3], co[3]), b3[a*4+3]);

    // anchor (numpy f64 path, whs pre-cast to f32)
    const int ay = p / FW, ax = p % FW;
    const double cxd = (ax + 0.5) * 16.0;
    const double cyd = (ay + 0.5) * 16.0;
    const int si = a / 3, ri = a % 3;
    const double sz = (si == 0) ? 32.0 : (si == 1) ? 64.0 : 128.0;
    const double rr = (ri == 0) ? 0.5 : (ri == 1) ? 1.0 : 2.0;
    const float hf = (float)(sz * sqrt(rr));
    const float wf = (float)(sz / sqrt(rr));
    const float ax1 = (float)(cxd - (double)wf * 0.5);
    const float ay1 = (float)(cyd - (double)hf * 0.5);
    const float ax2 = (float)(cxd + (double)wf * 0.5);
    const float ay2 = (float)(cyd + (double)hf * 0.5);

    // decode (f32 like reference; exp via double = correctly-rounded f32 exp)
    const float aw = __fsub_rn(ax2, ax1), ah = __fsub_rn(ay2, ay1);
    const float acx = __fadd_rn(ax1, __fmul_rn(0.5f, aw));
    const float acy = __fadd_rn(ay1, __fmul_rn(0.5f, ah));
    const float pcx = __fadd_rn(acx, __fmul_rn(o0, aw));
    const float pcy = __fadd_rn(acy, __fmul_rn(o1, ah));
    const float pw  = __fmul_rn(aw, (float)exp((double)o2));
    const float ph  = __fmul_rn(ah, (float)exp((double)o3));
    float x1 = __fsub_rn(pcx, __fmul_rn(0.5f, pw));
    float y1 = __fsub_rn(pcy, __fmul_rn(0.5f, ph));
    float x2 = __fadd_rn(pcx, __fmul_rn(0.5f, pw));
    float y2 = __fadd_rn(pcy, __fmul_rn(0.5f, ph));
    x1 = fminf(fmaxf(x1, 0.f), IMGW);
    y1 = fminf(fmaxf(y1, 0.f), IMGH);
    x2 = fminf(fmaxf(x2, 0.f), IMGW);
    y2 = fminf(fmaxf(y2, 0.f), IMGH);

    const float wb = x2 - x1, hb = y2 - y1;
    const bool valid = (wb >= 0.001f) && (hb >= 0.001f) && (s >= 0.5f);

    boxes[j] = make_float4(x1, y1, x2, y2);
    ss[j]    = s;
    keep[j]  = valid ? 1 : 0;
    __syncthreads();

    const float4 mb = boxes[j];
    const float myarea = (mb.z - mb.x) * (mb.w - mb.y);

    for (int i = 0; i < PRE - 1; i++) {
        __syncthreads();
        if (j > i && keep[i]) {
            float4 bi = boxes[i];
            float ltx = fmaxf(bi.x, mb.x), lty = fmaxf(bi.y, mb.y);
            float rbx = fminf(bi.z, mb.z), rby = fminf(bi.w, mb.w);
            float iw = fmaxf(rbx - ltx, 0.f), ih = fmaxf(rby - lty, 0.f);
            float inter = iw * ih;
            float ai = (bi.z - bi.x) * (bi.w - bi.y);
            float iou = inter / (ai + myarea - inter + 1e-9f);
            if (iou > 0.7f) keep[j] = 0;
        }
    }
    __syncthreads();

    const int lane = j & 31, warp = j >> 5;
    unsigned int m = __ballot_sync(0xffffffffu, keep[j] != 0);
    int pre = __popc(m & ((1u << lane) - 1u));
    if (lane == 0) warpcnt[warp] = __popc(m);
    __syncthreads();
    int base = 0, total = 0;
#pragma unroll
    for (int wi = 0; wi < 16; wi++) {
        int c = warpcnt[wi];
        if (wi < warp) base += c;
        total += c;
    }
    const int rank = base + pre;

    float* ob = out + (size_t)b * POST * 4;
    float* os = out + (size_t)BATCH * POST * 4 + (size_t)b * POST;

    if (j < POST && j >= total) {
        ob[j*4+0] = 0.f; ob[j*4+1] = 0.f; ob[j*4+2] = 0.f; ob[j*4+3] = 0.f;
        os[j] = 0.f;
    }
    if (keep[j] && rank < POST) {
        ob[rank*4+0] = mb.x; ob[rank*4+1] = mb.y;
        ob[rank*4+2] = mb.z; ob[rank*4+3] = mb.w;
        os[rank] = ss[j];
    }
}

// =========================== host launcher ==============================
extern "C" void kernel_launch(void* const* d_in, const int* in_sizes, int n_in,
                              void* d_out, int out_size)
{
    const float* fm = (const float*)d_in[0];
    const float* w1 = (const float*)d_in[1];
    const float* b1 = (const float*)d_in[2];
    const float* w2 = (const float*)d_in[3];
    const float* b2 = (const float*)d_in[4];
    const float* w3 = (const float*)d_in[5];
    const float* b3 = (const float*)d_in[6];
    float* out = (float*)d_out;

    conv3x3_kernel<<<dim3(40, 8, BATCH), 256>>>(fm, w1, b1);
    cls_kernel<<<dim3((HW + 255) / 256, BATCH), 256>>>(w2, b2);

    const int topk_smem = 32768*4 + 1024*4 + 1024*8;
    cudaFuncSetAttribute(topk_kernel,
                         cudaFuncAttributeMaxDynamicSharedMemorySize, topk_smem);
    topk_kernel<<<BATCH, 1024, topk_smem>>>();

    const int prop_smem = W3S_FLOATS*4 + PRE*16 + PRE*4 + PRE*4;
    cudaFuncSetAttribute(proposal_kernel,
                         cudaFuncAttributeMaxDynamicSharedMemorySize, prop_smem);
    proposal_kernel<<<BATCH, PRE, prop_smem>>>(w3, b3, out);
}

// round 4
// speedup vs baseline: 1.1537x; 1.1537x over previous
#include <cuda_runtime.h>
#include <cuda_bf16.h>
#include <math.h>

#define BATCH 16
#define CIN   512
#define FH    50
#define FW    50
#define HW    2500
#define NANCH 9
#define NTOT  (HW*NANCH)      // 22500
#define PRE   512
#define POST  128
#define IMGW  800.0f
#define IMGH  800.0f

// Kahan compensated accumulation, contraction-proof via intrinsics.
#define KAHAN_ADD(s, c, p) do {                        \
    float _y = __fsub_rn((p), (c));                    \
    float _t = __fadd_rn((s), _y);                     \
    (c) = __fsub_rn(__fsub_rn(_t, (s)), _y);           \
    (s) = _t;                                          \
} while (0)

#define COMP(v,i) ((i)==0?(v).x:((i)==1?(v).y:((i)==2?(v).z:(v).w)))

// ---------------- device scratch (static, no allocation) ----------------
__device__ float g_shared[(size_t)BATCH*CIN*HW];   // post-ReLU conv1 activations
__device__ float g_scores[(size_t)BATCH*NTOT];     // sigmoid cls scores, [b][p*9+a]
__device__ int   g_topidx[BATCH*PRE];
__device__ float g_topscore[BATCH*PRE];

// ================= K1: 3x3 conv (512->512) + bias + ReLU =================
// Blocked compensation: per input channel, the 9-tap contribution is computed
// with three 3-term FFMA chains (+2 adds) at small magnitude, then Kahan-added
// into the cross-channel accumulator (exact). ~1.67 ops/MAC, rel-err ~8e-8.
__global__ __launch_bounds__(256) void conv3x3_kernel(
    const float* __restrict__ x, const float* __restrict__ w1,
    const float* __restrict__ b1)
{
    __shared__ float Ws[9][64];
    __shared__ float Xs[5][52];

    const int bidx = blockIdx.z;
    const int oc0  = blockIdx.y * 64;
    const int p0   = blockIdx.x * 64;
    const int tid  = threadIdx.x;
    const int tx   = tid & 15;     // pixel group
    const int ty   = tid >> 4;     // oc group

    const int yA = p0 / FW;

    int  pj[4], rj[4], cj[4];
    bool inb[4];
#pragma unroll
    for (int jj = 0; jj < 4; jj++) {
        int p = p0 + tx*4 + jj;
        pj[jj] = p;
        int py = p / FW, pxx = p % FW;
        rj[jj] = py - yA + 1;
        cj[jj] = pxx + 1;
        inb[jj] = (p < HW);
    }

    float acc[4][4], cmp[4][4];
#pragma unroll
    for (int i = 0; i < 4; i++)
#pragma unroll
        for (int j = 0; j < 4; j++) { acc[i][j] = 0.f; cmp[i][j] = 0.f; }

    const float* xb = x + (size_t)bidx * CIN * HW;

    for (int ic = 0; ic < CIN; ic++) {
        for (int i = tid; i < 576; i += 256) {
            int t = i / 64, o = i % 64;
            Ws[t][o] = w1[((size_t)(oc0 + o)) * (CIN*9) + ic*9 + t];
        }
        const float* xc = xb + (size_t)ic * HW;
        for (int i = tid; i < 5*52; i += 256) {
            int rr = i / 52, cc = i % 52;
            int yy = yA - 1 + rr, xx = cc - 1;
            Xs[rr][cc] = (yy >= 0 && yy < FH && xx >= 0 && xx < FW)
                             ? xc[yy*FW + xx] : 0.f;
        }
        __syncthreads();

        // weights for this ic, 4 ocs at once (vector smem loads)
        float4 wv[9];
#pragma unroll
        for (int t = 0; t < 9; t++)
            wv[t] = *(const float4*)&Ws[t][ty*4];

#pragma unroll
        for (int jj = 0; jj < 4; jj++) {
            float xv[9];
#pragma unroll
            for (int t = 0; t < 9; t++)
                xv[t] = Xs[rj[jj] + t/3 - 1][cj[jj] + t%3 - 1];

#pragma unroll
            for (int i = 0; i < 4; i++) {
                float d0 = __fmul_rn(COMP(wv[0],i), xv[0]);
                d0 = __fmaf_rn(COMP(wv[1],i), xv[1], d0);
                d0 = __fmaf_rn(COMP(wv[2],i), xv[2], d0);
                float d1 = __fmul_rn(COMP(wv[3],i), xv[3]);
                d1 = __fmaf_rn(COMP(wv[4],i), xv[4], d1);
                d1 = __fmaf_rn(COMP(wv[5],i), xv[5], d1);
                float d2 = __fmul_rn(COMP(wv[6],i), xv[6]);
                d2 = __fmaf_rn(COMP(wv[7],i), xv[7], d2);
                d2 = __fmaf_rn(COMP(wv[8],i), xv[8], d2);
                float d = __fadd_rn(__fadd_rn(d0, d1), d2);
                KAHAN_ADD(acc[i][jj], cmp[i][jj], d);
            }
        }
        __syncthreads();
    }

#pragma unroll
    for (int ii = 0; ii < 4; ii++) {
        int oc = oc0 + ty*4 + ii;
        float bias = b1[oc];
#pragma unroll
        for (int jj = 0; jj < 4; jj++) {
            if (inb[jj]) {
                float r = __fsub_rn(acc[ii][jj], cmp[ii][jj]);
                float v = __fadd_rn(r, bias);
                g_shared[((size_t)bidx*CIN + oc)*HW + pj[jj]] = fmaxf(v, 0.f);
            }
        }
    }
}

// ================= K2: 1x1 cls conv (512->9) + sigmoid ==================
__global__ __launch_bounds__(256) void cls_kernel(
    const float* __restrict__ w2, const float* __restrict__ b2)
{
    __shared__ float w2s[9][512];
    const int b = blockIdx.y;
    const int p = blockIdx.x * 256 + threadIdx.x;
    for (int i = threadIdx.x; i < 9*512; i += 256)
        w2s[i/512][i%512] = w2[i];
    __syncthreads();
    if (p >= HW) return;

    float acc[9], cmp[9];
#pragma unroll
    for (int a = 0; a < 9; a++) { acc[a] = 0.f; cmp[a] = 0.f; }

    const float* sp = g_shared + (size_t)b * CIN * HW + p;
    for (int c = 0; c < CIN; c++) {
        float v = sp[(size_t)c * HW];
#pragma unroll
        for (int a = 0; a < 9; a++)
            KAHAN_ADD(acc[a], cmp[a], __fmul_rn(v, w2s[a][c]));
    }
    float* outp = g_scores + (size_t)b * NTOT + (size_t)p * 9;
#pragma unroll
    for (int a = 0; a < 9; a++) {
        float logit = __fadd_rn(__fsub_rn(acc[a], cmp[a]), b2[a]);
        double sg = 1.0 / (1.0 + exp(-(double)logit));
        outp[a] = (float)sg;
    }
}

// ================= K3: exact per-image top-512 (sorted) ==================
__global__ __launch_bounds__(1024) void topk_kernel()
{
    extern __shared__ unsigned char smraw[];
    unsigned int* hist = (unsigned int*)smraw;                 // 32768
    unsigned int* csum = hist + 32768;                         // 1024
    unsigned long long* cand = (unsigned long long*)(csum + 1024); // 1024
    __shared__ int s_tb, s_cntgt, s_thr, s_cnt;

    const int b = blockIdx.x, tid = threadIdx.x;
    const float* sc = g_scores + (size_t)b * NTOT;

    for (int i = tid; i < 32768; i += 1024) hist[i] = 0;
    __syncthreads();
    for (int i = tid; i < NTOT; i += 1024) {
        unsigned int bits = __float_as_uint(sc[i]);
        atomicAdd(&hist[bits >> 15], 1u);
    }
    __syncthreads();
    { unsigned int cs = 0;
#pragma unroll 4
      for (int k = 0; k < 32; k++) cs += hist[tid*32 + k];
      csum[tid] = cs; }
    __syncthreads();
    if (tid == 0) {
        unsigned int accum = 0;
        int ch = 1023;
        for (; ch > 0; ch--) { if (accum + csum[ch] >= PRE) break; accum += csum[ch]; }
        int bk = ch*32 + 31;
        for (; bk > ch*32; bk--) { if (accum + hist[bk] >= PRE) break; accum += hist[bk]; }
        s_tb = bk; s_cntgt = (int)accum;
    }
    __syncthreads();
    const int tb = s_tb, cntgt = s_cntgt;

    for (int i = tid; i < 32768; i += 1024) hist[i] = 0;
    __syncthreads();
    for (int i = tid; i < NTOT; i += 1024) {
        unsigned int bits = __float_as_uint(sc[i]);
        if ((int)(bits >> 15) == tb) atomicAdd(&hist[bits & 0x7FFF], 1u);
    }
    __syncthreads();
    { unsigned int cs = 0;
#pragma unroll 4
      for (int k = 0; k < 32; k++) cs += hist[tid*32 + k];
      csum[tid] = cs; }
    __syncthreads();
    if (tid == 0) {
        unsigned int accum = (unsigned int)cntgt;
        int ch = 1023;
        for (; ch > 0; ch--) { if (accum + csum[ch] >= PRE) break; accum += csum[ch]; }
        int bk = ch*32 + 31;
        for (; bk > ch*32; bk--) { if (accum + hist[bk] >= PRE) break; accum += hist[bk]; }
        s_thr = (tb << 15) | bk;
        s_cnt = 0;
    }
    __syncthreads();
    const unsigned int thrbits = (unsigned int)s_thr;

    for (int i = tid; i < NTOT; i += 1024) {
        unsigned int bits = __float_as_uint(sc[i]);
        if (bits >= thrbits) {
            int pos = atomicAdd(&s_cnt, 1);
            if (pos < 1024)
                cand[pos] = ((unsigned long long)bits << 32) |
                            (unsigned long long)(0xFFFFFFFFu - (unsigned int)i);
        }
    }
    __syncthreads();
    int cnt = s_cnt; if (cnt > 1024) cnt = 1024;
    if (tid >= cnt) cand[tid] = 0ULL;
    __syncthreads();

    for (int k = 2; k <= 1024; k <<= 1) {
        for (int j = k >> 1; j > 0; j >>= 1) {
            int ixj = tid ^ j;
            if (ixj > tid) {
                unsigned long long a = cand[tid], c = cand[ixj];
                bool up = ((tid & k) == 0);
                bool sw = up ? (a < c) : (a > c);
                if (sw) { cand[tid] = c; cand[ixj] = a; }
            }
            __syncthreads();
        }
    }

    if (tid < PRE) {
        unsigned long long key = cand[tid];
        unsigned int idx = 0xFFFFFFFFu - (unsigned int)(key & 0xFFFFFFFFull);
        g_topidx[b*PRE + tid]   = (int)idx;
        g_topscore[b*PRE + tid] = __uint_as_float((unsigned int)(key >> 32));
    }
}

// ====== K4: offsets@selected + anchors + decode + clip + NMS + output ====
#define W3S_FLOATS (36*513)    // multiple of 4 -> 16B aligned end
__global__ __launch_bounds__(512) void proposal_kernel(
    const float* __restrict__ w3, const float* __restrict__ b3,
    float* __restrict__ out)
{
    extern __shared__ float sm[];
    float*  w3s   = sm;
    float4* boxes = (float4*)(sm + W3S_FLOATS);
    float*  ss    = (float*)(boxes + PRE);
    int*    keep  = (int*)(ss + PRE);
    __shared__ int warpcnt[16];

    const int b = blockIdx.x;
    const int j = threadIdx.x;

    for (int i = j; i < 36*512; i += 512) {
        int row = i >> 9, c = i & 511;
        w3s[row*513 + c] = w3[i];
    }
    __syncthreads();

    const int   idx = g_topidx[b*PRE + j];
    const float s   = g_topscore[b*PRE + j];
    const int p = idx / 9, a = idx % 9;

    float so[4] = {0.f,0.f,0.f,0.f}, co[4] = {0.f,0.f,0.f,0.f};
    {
        const float* col = g_shared + (size_t)b * CIN * HW + p;
        const float* w0 = w3s + (a*4+0)*513;
        const float* w1r= w3s + (a*4+1)*513;
        const float* w2r= w3s + (a*4+2)*513;
        const float* w3r= w3s + (a*4+3)*513;
        for (int c = 0; c < CIN; c++) {
            float v = col[(size_t)c * HW];
            KAHAN_ADD(so[0], co[0], __fmul_rn(v, w0[c]));
            KAHAN_ADD(so[1], co[1], __fmul_rn(v, w1r[c]));
            KAHAN_ADD(so[2], co[2], __fmul_rn(v, w2r[c]));
            KAHAN_ADD(so[3], co[3], __fmul_rn(v, w3r[c]));
        }
    }
    const float o0 = __fadd_rn(__fsub_rn(so[0], co[0]), b3[a*4+0]);
    const float o1 = __fadd_rn(__fsub_rn(so[1], co[1]), b3[a*4+1]);
    const float o2 = __fadd_rn(__fsub_rn(so[2], co[2]), b3[a*4+2]);
    const float o3 = __fadd_rn(__fsub_rn(so[3], co[3]), b3[a*4+3]);

    const int ay = p / FW, ax = p % FW;
    const double cxd = (ax + 0.5) * 16.0;
    const double cyd = (ay + 0.5) * 16.0;
    const int si = a / 3, ri = a % 3;
    const double sz = (si == 0) ? 32.0 : (si == 1) ? 64.0 : 128.0;
    const double rr = (ri == 0) ? 0.5 : (ri == 1) ? 1.0 : 2.0;
    const float hf = (float)(sz * sqrt(rr));
    const float wf = (float)(sz / sqrt(rr));
    const float ax1 = (float)(cxd - (double)wf * 0.5);
    const float ay1 = (float)(cyd - (double)hf * 0.5);
    const float ax2 = (float)(cxd + (double)wf * 0.5);
    const float ay2 = (float)(cyd + (double)hf * 0.5);

    const float aw = __fsub_rn(ax2, ax1), ah = __fsub_rn(ay2, ay1);
    const float acx = __fadd_rn(ax1, __fmul_rn(0.5f, aw));
    const float acy = __fadd_rn(ay1, __fmul_rn(0.5f, ah));
    const float pcx = __fadd_rn(acx, __fmul_rn(o0, aw));
    const float pcy = __fadd_rn(acy, __fmul_rn(o1, ah));
    const float pw  = __fmul_rn(aw, (float)exp((double)o2));
    const float ph  = __fmul_rn(ah, (float)exp((double)o3));
    float x1 = __fsub_rn(pcx, __fmul_rn(0.5f, pw));
    float y1 = __fsub_rn(pcy, __fmul_rn(0.5f, ph));
    float x2 = __fadd_rn(pcx, __fmul_rn(0.5f, pw));
    float y2 = __fadd_rn(pcy, __fmul_rn(0.5f, ph));
    x1 = fminf(fmaxf(x1, 0.f), IMGW);
    y1 = fminf(fmaxf(y1, 0.f), IMGH);
    x2 = fminf(fmaxf(x2, 0.f), IMGW);
    y2 = fminf(fmaxf(y2, 0.f), IMGH);

    const float wb = x2 - x1, hb = y2 - y1;
    const bool valid = (wb >= 0.001f) && (hb >= 0.001f) && (s >= 0.5f);

    boxes[j] = make_float4(x1, y1, x2, y2);
    ss[j]    = s;
    keep[j]  = valid ? 1 : 0;
    __syncthreads();

    const float4 mb = boxes[j];
    const float myarea = (mb.z - mb.x) * (mb.w - mb.y);

    for (int i = 0; i < PRE - 1; i++) {
        __syncthreads();
        if (j > i && keep[i]) {
            float4 bi = boxes[i];
            float ltx = fmaxf(bi.x, mb.x), lty = fmaxf(bi.y, mb.y);
            float rbx = fminf(bi.z, mb.z), rby = fminf(bi.w, mb.w);
            float iw = fmaxf(rbx - ltx, 0.f), ih = fmaxf(rby - lty, 0.f);
            float inter = iw * ih;
            float ai = (bi.z - bi.x) * (bi.w - bi.y);
            float iou = inter / (ai + myarea - inter + 1e-9f);
            if (iou > 0.7f) keep[j] = 0;
        }
    }
    __syncthreads();

    const int lane = j & 31, warp = j >> 5;
    unsigned int m = __ballot_sync(0xffffffffu, keep[j] != 0);
    int pre = __popc(m & ((1u << lane) - 1u));
    if (lane == 0) warpcnt[warp] = __popc(m);
    __syncthreads();
    int base = 0, total = 0;
#pragma unroll
    for (int wi = 0; wi < 16; wi++) {
        int c = warpcnt[wi];
        if (wi < warp) base += c;
        total += c;
    }
    const int rank = base + pre;

    float* ob = out + (size_t)b * POST * 4;
    float* os = out + (size_t)BATCH * POST * 4 + (size_t)b * POST;

    if (j < POST && j >= total) {
        ob[j*4+0] = 0.f; ob[j*4+1] = 0.f; ob[j*4+2] = 0.f; ob[j*4+3] = 0.f;
        os[j] = 0.f;
    }
    if (keep[j] && rank < POST) {
        ob[rank*4+0] = mb.x; ob[rank*4+1] = mb.y;
        ob[rank*4+2] = mb.z; ob[rank*4+3] = mb.w;
        os[rank] = ss[j];
    }
}

// =========================== host launcher ==============================
extern "C" void kernel_launch(void* const* d_in, const int* in_sizes, int n_in,
                              void* d_out, int out_size)
{
    const float* fm = (const float*)d_in[0];
    const float* w1 = (const float*)d_in[1];
    const float* b1 = (const float*)d_in[2];
    const float* w2 = (const float*)d_in[3];
    const float* b2 = (const float*)d_in[4];
    const float* w3 = (const float*)d_in[5];
    const float* b3 = (const float*)d_in[6];
    float* out = (float*)d_out;

    conv3x3_kernel<<<dim3(40, 8, BATCH), 256>>>(fm, w1, b1);
    cls_kernel<<<dim3((HW + 255) / 256, BATCH), 256>>>(w2, b2);

    const int topk_smem = 32768*4 + 1024*4 + 1024*8;
    cudaFuncSetAttribute(topk_kernel,
                         cudaFuncAttributeMaxDynamicSharedMemorySize, topk_smem);
    topk_kernel<<<BATCH, 1024, topk_smem>>>();

    const int prop_smem = W3S_FLOATS*4 + PRE*16 + PRE*4 + PRE*4;
    cudaFuncSetAttribute(proposal_kernel,
                         cudaFuncAttributeMaxDynamicSharedMemorySize, prop_smem);
    proposal_kernel<<<BATCH, PRE, prop_smem>>>(w3, b3, out);
}

// round 5
// speedup vs baseline: 1.7884x; 1.5501x over previous
#include <cuda_runtime.h>
#include <cuda_bf16.h>
#include <math.h>

#define BATCH 16
#define CIN   512
#define FH    50
#define FW    50
#define HW    2500
#define NANCH 9
#define NTOT  (HW*NANCH)      // 22500
#define PRE   512
#define POST  128
#define IMGW  800.0f
#define IMGH  800.0f
#define KB    4               // input channels per staging step

// Kahan compensated accumulation, contraction-proof via intrinsics.
#define KAHAN_ADD(s, c, p) do {                        \
    float _y = __fsub_rn((p), (c));                    \
    float _t = __fadd_rn((s), _y);                     \
    (c) = __fsub_rn(__fsub_rn(_t, (s)), _y);           \
    (s) = _t;                                          \
} while (0)

#define COMP(v,i) ((i)==0?(v).x:((i)==1?(v).y:((i)==2?(v).z:(v).w)))

// ---------------- device scratch (static, no allocation) ----------------
__device__ float g_shared[(size_t)BATCH*CIN*HW];   // post-ReLU conv1 activations
__device__ float g_scores[(size_t)BATCH*NTOT];     // sigmoid cls scores
__device__ int   g_topidx[BATCH*PRE];
__device__ float g_topscore[BATCH*PRE];
__device__ float g_w1t[4608*512];                  // w1 transposed: [ic*9+t][oc]

// ================= K0: transpose w1 [oc][4608] -> [4608][oc] ============
__global__ __launch_bounds__(256) void transpose_w1_kernel(
    const float* __restrict__ w1)
{
    __shared__ float t[32][33];
    const int r0 = blockIdx.x * 32;   // 4608/32 = 144
    const int c0 = blockIdx.y * 32;   // 512/32  = 16
    const int tx = threadIdx.x & 31, ty = threadIdx.x >> 5;  // 32x8
#pragma unroll
    for (int i = 0; i < 4; i++) {
        int oc = c0 + ty + i*8;       // row of w1
        int r  = r0 + tx;             // col of w1
        t[ty + i*8][tx] = w1[(size_t)oc * 4608 + r];
    }
    __syncthreads();
#pragma unroll
    for (int i = 0; i < 4; i++) {
        int r  = r0 + ty + i*8;
        int oc = c0 + tx;
        g_w1t[(size_t)r * 512 + oc] = t[tx][ty + i*8];
    }
}

// ================= K1: 3x3 conv (512->512) + bias + ReLU =================
// Coalesced weight staging from g_w1t; KB input channels per sync stage.
// Inner math identical to R4 (blocked-Kahan, rel_err ~5e-8 proven).
__global__ __launch_bounds__(256) void conv3x3_kernel(
    const float* __restrict__ x, const float* __restrict__ b1)
{
    __shared__ float Ws[KB*9][64];     // taps-major rows, oc cols (coalesced STS)
    __shared__ float Xs[KB][5][52];

    const int bidx = blockIdx.z;
    const int oc0  = blockIdx.y * 64;
    const int p0   = blockIdx.x * 64;
    const int tid  = threadIdx.x;
    const int tx   = tid & 15;     // pixel group
    const int ty   = tid >> 4;     // oc group

    const int yA = p0 / FW;

    int  pj[4], rj[4], cj[4];
    bool inb[4];
#pragma unroll
    for (int jj = 0; jj < 4; jj++) {
        int p = p0 + tx*4 + jj;
        pj[jj] = p;
        int py = p / FW, pxx = p % FW;
        rj[jj] = py - yA + 1;
        cj[jj] = pxx + 1;
        inb[jj] = (p < HW);
    }

    float acc[4][4], cmp[4][4];
#pragma unroll
    for (int i = 0; i < 4; i++)
#pragma unroll
        for (int j = 0; j < 4; j++) { acc[i][j] = 0.f; cmp[i][j] = 0.f; }

    const float* xb = x + (size_t)bidx * CIN * HW;

    for (int ic0 = 0; ic0 < CIN; ic0 += KB) {
        // ---- stage KB ics of weights (coalesced float4) + inputs ----
        // weights: rows r = ic*9+t for ic in [ic0,ic0+KB), cols oc0..oc0+63
        // KB*9*64 = 2304 floats = 576 float4
        for (int i = tid; i < KB*9*16; i += 256) {
            int row = i >> 4;              // 0..35
            int o4  = (i & 15) << 2;       // 0,4,...,60
            float4 v = *(const float4*)&g_w1t[(size_t)(ic0*9 + row) * 512 + oc0 + o4];
            *(float4*)&Ws[row][o4] = v;
        }
        // inputs: KB patches of 5x52
        for (int i = tid; i < KB*260; i += 256) {
            int k  = i / 260;
            int rr = (i % 260) / 52, cc = i % 52;
            int yy = yA - 1 + rr, xx = cc - 1;
            Xs[k][rr][cc] = (yy >= 0 && yy < FH && xx >= 0 && xx < FW)
                    ? xb[(size_t)(ic0 + k) * HW + yy*FW + xx] : 0.f;
        }
        __syncthreads();

#pragma unroll
        for (int k = 0; k < KB; k++) {
            float4 wv[9];
#pragma unroll
            for (int t = 0; t < 9; t++)
                wv[t] = *(const float4*)&Ws[k*9 + t][ty*4];

#pragma unroll
            for (int jj = 0; jj < 4; jj++) {
                float xv[9];
#pragma unroll
                for (int t = 0; t < 9; t++)
                    xv[t] = Xs[k][rj[jj] + t/3 - 1][cj[jj] + t%3 - 1];

#pragma unroll
                for (int i = 0; i < 4; i++) {
                    float d0 = __fmul_rn(COMP(wv[0],i), xv[0]);
                    d0 = __fmaf_rn(COMP(wv[1],i), xv[1], d0);
                    d0 = __fmaf_rn(COMP(wv[2],i), xv[2], d0);
                    float d1 = __fmul_rn(COMP(wv[3],i), xv[3]);
                    d1 = __fmaf_rn(COMP(wv[4],i), xv[4], d1);
                    d1 = __fmaf_rn(COMP(wv[5],i), xv[5], d1);
                    float d2 = __fmul_rn(COMP(wv[6],i), xv[6]);
                    d2 = __fmaf_rn(COMP(wv[7],i), xv[7], d2);
                    d2 = __fmaf_rn(COMP(wv[8],i), xv[8], d2);
                    float d = __fadd_rn(__fadd_rn(d0, d1), d2);
                    KAHAN_ADD(acc[i][jj], cmp[i][jj], d);
                }
            }
        }
        __syncthreads();
    }

#pragma unroll
    for (int ii = 0; ii < 4; ii++) {
        int oc = oc0 + ty*4 + ii;
        float bias = b1[oc];
#pragma unroll
        for (int jj = 0; jj < 4; jj++) {
            if (inb[jj]) {
                float r = __fsub_rn(acc[ii][jj], cmp[ii][jj]);
                float v = __fadd_rn(r, bias);
                g_shared[((size_t)bidx*CIN + oc)*HW + pj[jj]] = fmaxf(v, 0.f);
            }
        }
    }
}

// ================= K2: 1x1 cls conv (512->9) + sigmoid ==================
__global__ __launch_bounds__(256) void cls_kernel(
    const float* __restrict__ w2, const float* __restrict__ b2)
{
    __shared__ float w2s[9][512];
    const int b = blockIdx.y;
    const int p = blockIdx.x * 256 + threadIdx.x;
    for (int i = threadIdx.x; i < 9*512; i += 256)
        w2s[i/512][i%512] = w2[i];
    __syncthreads();
    if (p >= HW) return;

    float acc[9], cmp[9];
#pragma unroll
    for (int a = 0; a < 9; a++) { acc[a] = 0.f; cmp[a] = 0.f; }

    const float* sp = g_shared + (size_t)b * CIN * HW + p;
    for (int c = 0; c < CIN; c++) {
        float v = sp[(size_t)c * HW];
#pragma unroll
        for (int a = 0; a < 9; a++)
            KAHAN_ADD(acc[a], cmp[a], __fmul_rn(v, w2s[a][c]));
    }
    float* outp = g_scores + (size_t)b * NTOT + (size_t)p * 9;
#pragma unroll
    for (int a = 0; a < 9; a++) {
        float logit = __fadd_rn(__fsub_rn(acc[a], cmp[a]), b2[a]);
        double sg = 1.0 / (1.0 + exp(-(double)logit));
        outp[a] = (float)sg;
    }
}

// ================= K3: exact per-image top-512 (sorted) ==================
__global__ __launch_bounds__(1024) void topk_kernel()
{
    extern __shared__ unsigned char smraw[];
    unsigned int* hist = (unsigned int*)smraw;                 // 32768
    unsigned int* csum = hist + 32768;                         // 1024
    unsigned long long* cand = (unsigned long long*)(csum + 1024); // 1024
    __shared__ int s_tb, s_cntgt, s_thr, s_cnt;

    const int b = blockIdx.x, tid = threadIdx.x;
    const float* sc = g_scores + (size_t)b * NTOT;

    for (int i = tid; i < 32768; i += 1024) hist[i] = 0;
    __syncthreads();
    for (int i = tid; i < NTOT; i += 1024) {
        unsigned int bits = __float_as_uint(sc[i]);
        atomicAdd(&hist[bits >> 15], 1u);
    }
    __syncthreads();
    { unsigned int cs = 0;
#pragma unroll 4
      for (int k = 0; k < 32; k++) cs += hist[tid*32 + k];
      csum[tid] = cs; }
    __syncthreads();
    if (tid == 0) {
        unsigned int accum = 0;
        int ch = 1023;
        for (; ch > 0; ch--) { if (accum + csum[ch] >= PRE) break; accum += csum[ch]; }
        int bk = ch*32 + 31;
        for (; bk > ch*32; bk--) { if (accum + hist[bk] >= PRE) break; accum += hist[bk]; }
        s_tb = bk; s_cntgt = (int)accum;
    }
    __syncthreads();
    const int tb = s_tb, cntgt = s_cntgt;

    for (int i = tid; i < 32768; i += 1024) hist[i] = 0;
    __syncthreads();
    for (int i = tid; i < NTOT; i += 1024) {
        unsigned int bits = __float_as_uint(sc[i]);
        if ((int)(bits >> 15) == tb) atomicAdd(&hist[bits & 0x7FFF], 1u);
    }
    __syncthreads();
    { unsigned int cs = 0;
#pragma unroll 4
      for (int k = 0; k < 32; k++) cs += hist[tid*32 + k];
      csum[tid] = cs; }
    __syncthreads();
    if (tid == 0) {
        unsigned int accum = (unsigned int)cntgt;
        int ch = 1023;
        for (; ch > 0; ch--) { if (accum + csum[ch] >= PRE) break; accum += csum[ch]; }
        int bk = ch*32 + 31;
        for (; bk > ch*32; bk--) { if (accum + hist[bk] >= PRE) break; accum += hist[bk]; }
        s_thr = (tb << 15) | bk;
        s_cnt = 0;
    }
    __syncthreads();
    const unsigned int thrbits = (unsigned int)s_thr;

    for (int i = tid; i < NTOT; i += 1024) {
        unsigned int bits = __float_as_uint(sc[i]);
        if (bits >= thrbits) {
            int pos = atomicAdd(&s_cnt, 1);
            if (pos < 1024)
                cand[pos] = ((unsigned long long)bits << 32) |
                            (unsigned long long)(0xFFFFFFFFu - (unsigned int)i);
        }
    }
    __syncthreads();
    int cnt = s_cnt; if (cnt > 1024) cnt = 1024;
    if (tid >= cnt) cand[tid] = 0ULL;
    __syncthreads();

    for (int k = 2; k <= 1024; k <<= 1) {
        for (int j = k >> 1; j > 0; j >>= 1) {
            int ixj = tid ^ j;
            if (ixj > tid) {
                unsigned long long a = cand[tid], c = cand[ixj];
                bool up = ((tid & k) == 0);
                bool sw = up ? (a < c) : (a > c);
                if (sw) { cand[tid] = c; cand[ixj] = a; }
            }
            __syncthreads();
        }
    }

    if (tid < PRE) {
        unsigned long long key = cand[tid];
        unsigned int idx = 0xFFFFFFFFu - (unsigned int)(key & 0xFFFFFFFFull);
        g_topidx[b*PRE + tid]   = (int)idx;
        g_topscore[b*PRE + tid] = __uint_as_float((unsigned int)(key >> 32));
    }
}

// ====== K4: offsets@selected + anchors + decode + clip + NMS + output ====
#define W3S_FLOATS (36*513)    // multiple of 4 -> 16B aligned end
__global__ __launch_bounds__(512) void proposal_kernel(
    const float* __restrict__ w3, const float* __restrict__ b3,
    float* __restrict__ out)
{
    extern __shared__ float sm[];
    float*  w3s   = sm;
    float4* boxes = (float4*)(sm + W3S_FLOATS);
    float*  ss    = (float*)(boxes + PRE);
    int*    keep  = (int*)(ss + PRE);
    __shared__ int warpcnt[16];

    const int b = blockIdx.x;
    const int j = threadIdx.x;

    for (int i = j; i < 36*512; i += 512) {
        int row = i >> 9, c = i & 511;
        w3s[row*513 + c] = w3[i];
    }
    __syncthreads();

    const int   idx = g_topidx[b*PRE + j];
    const float s   = g_topscore[b*PRE + j];
    const int p = idx / 9, a = idx % 9;

    float so[4] = {0.f,0.f,0.f,0.f}, co[4] = {0.f,0.f,0.f,0.f};
    {
        const float* col = g_shared + (size_t)b * CIN * HW + p;
        const float* w0 = w3s + (a*4+0)*513;
        const float* w1r= w3s + (a*4+1)*513;
        const float* w2r= w3s + (a*4+2)*513;
        const float* w3r= w3s + (a*4+3)*513;
        for (int c = 0; c < CIN; c++) {
            float v = col[(size_t)c * HW];
            KAHAN_ADD(so[0], co[0], __fmul_rn(v, w0[c]));
            KAHAN_ADD(so[1], co[1], __fmul_rn(v, w1r[c]));
            KAHAN_ADD(so[2], co[2], __fmul_rn(v, w2r[c]));
            KAHAN_ADD(so[3], co[3], __fmul_rn(v, w3r[c]));
        }
    }
    const float o0 = __fadd_rn(__fsub_rn(so[0], co[0]), b3[a*4+0]);
    const float o1 = __fadd_rn(__fsub_rn(so[1], co[1]), b3[a*4+1]);
    const float o2 = __fadd_rn(__fsub_rn(so[2], co[2]), b3[a*4+2]);
    const float o3 = __fadd_rn(__fsub_rn(so[3], co[3]), b3[a*4+3]);

    const int ay = p / FW, ax = p % FW;
    const double cxd = (ax + 0.5) * 16.0;
    const double cyd = (ay + 0.5) * 16.0;
    const int si = a / 3, ri = a % 3;
    const double sz = (si == 0) ? 32.0 : (si == 1) ? 64.0 : 128.0;
    const double rr = (ri == 0) ? 0.5 : (ri == 1) ? 1.0 : 2.0;
    const float hf = (float)(sz * sqrt(rr));
    const float wf = (float)(sz / sqrt(rr));
    const float ax1 = (float)(cxd - (double)wf * 0.5);
    const float ay1 = (float)(cyd - (double)hf * 0.5);
    const float ax2 = (float)(cxd + (double)wf * 0.5);
    const float ay2 = (float)(cyd + (double)hf * 0.5);

    const float aw = __fsub_rn(ax2, ax1), ah = __fsub_rn(ay2, ay1);
    const float acx = __fadd_rn(ax1, __fmul_rn(0.5f, aw));
    const float acy = __fadd_rn(ay1, __fmul_rn(0.5f, ah));
    const float pcx = __fadd_rn(acx, __fmul_rn(o0, aw));
    const float pcy = __fadd_rn(acy, __fmul_rn(o1, ah));
    const float pw  = __fmul_rn(aw, (float)exp((double)o2));
    const float ph  = __fmul_rn(ah, (float)exp((double)o3));
    float x1 = __fsub_rn(pcx, __fmul_rn(0.5f, pw));
    float y1 = __fsub_rn(pcy, __fmul_rn(0.5f, ph));
    float x2 = __fadd_rn(pcx, __fmul_rn(0.5f, pw));
    float y2 = __fadd_rn(pcy, __fmul_rn(0.5f, ph));
    x1 = fminf(fmaxf(x1, 0.f), IMGW);
    y1 = fminf(fmaxf(y1, 0.f), IMGH);
    x2 = fminf(fmaxf(x2, 0.f), IMGW);
    y2 = fminf(fmaxf(y2, 0.f), IMGH);

    const float wb = x2 - x1, hb = y2 - y1;
    const bool valid = (wb >= 0.001f) && (hb >= 0.001f) && (s >= 0.5f);

    boxes[j] = make_float4(x1, y1, x2, y2);
    ss[j]    = s;
    keep[j]  = valid ? 1 : 0;
    __syncthreads();

    const float4 mb = boxes[j];
    const float myarea = (mb.z - mb.x) * (mb.w - mb.y);

    for (int i = 0; i < PRE - 1; i++) {
        __syncthreads();
        if (j > i && keep[i]) {
            float4 bi = boxes[i];
            float ltx = fmaxf(bi.x, mb.x), lty = fmaxf(bi.y, mb.y);
            float rbx = fminf(bi.z, mb.z), rby = fminf(bi.w, mb.w);
            float iw = fmaxf(rbx - ltx, 0.f), ih = fmaxf(rby - lty, 0.f);
            float inter = iw * ih;
            float ai = (bi.z - bi.x) * (bi.w - bi.y);
            float iou = inter / (ai + myarea - inter + 1e-9f);
            if (iou > 0.7f) keep[j] = 0;
        }
    }
    __syncthreads();

    const int lane = j & 31, warp = j >> 5;
    unsigned int m = __ballot_sync(0xffffffffu, keep[j] != 0);
    int pre = __popc(m & ((1u << lane) - 1u));
    if (lane == 0) warpcnt[warp] = __popc(m);
    __syncthreads();
    int base = 0, total = 0;
#pragma unroll
    for (int wi = 0; wi < 16; wi++) {
        int c = warpcnt[wi];
        if (wi < warp) base += c;
        total += c;
    }
    const int rank = base + pre;

    float* ob = out + (size_t)b * POST * 4;
    float* os = out + (size_t)BATCH * POST * 4 + (size_t)b * POST;

    if (j < POST && j >= total) {
        ob[j*4+0] = 0.f; ob[j*4+1] = 0.f; ob[j*4+2] = 0.f; ob[j*4+3] = 0.f;
        os[j] = 0.f;
    }
    if (keep[j] && rank < POST) {
        ob[rank*4+0] = mb.x; ob[rank*4+1] = mb.y;
        ob[rank*4+2] = mb.z; ob[rank*4+3] = mb.w;
        os[rank] = ss[j];
    }
}

// =========================== host launcher ==============================
extern "C" void kernel_launch(void* const* d_in, const int* in_sizes, int n_in,
                              void* d_out, int out_size)
{
    const float* fm = (const float*)d_in[0];
    const float* w1 = (const float*)d_in[1];
    const float* b1 = (const float*)d_in[2];
    const float* w2 = (const float*)d_in[3];
    const float* b2 = (const float*)d_in[4];
    const float* w3 = (const float*)d_in[5];
    const float* b3 = (const float*)d_in[6];
    float* out = (float*)d_out;

    // K0: transpose w1 -> g_w1t (coalesced weight access for K1)
    transpose_w1_kernel<<<dim3(144, 16), 256>>>(w1);

    // K1: conv3x3 + ReLU
    conv3x3_kernel<<<dim3(40, 8, BATCH), 256>>>(fm, b1);

    // K2: cls conv + sigmoid
    cls_kernel<<<dim3((HW + 255) / 256, BATCH), 256>>>(w2, b2);

    // K3: top-512 per image
    const int topk_smem = 32768*4 + 1024*4 + 1024*8;
    cudaFuncSetAttribute(topk_kernel,
                         cudaFuncAttributeMaxDynamicSharedMemorySize, topk_smem);
    topk_kernel<<<BATCH, 1024, topk_smem>>>();

    // K4: offsets + decode + NMS + output
    const int prop_smem = W3S_FLOATS*4 + PRE*16 + PRE*4 + PRE*4;
    cudaFuncSetAttribute(proposal_kernel,
                         cudaFuncAttributeMaxDynamicSharedMemorySize, prop_smem);
    proposal_kernel<<<BATCH, PRE, prop_smem>>>(w3, b3, out);
}